// round 4
// baseline (speedup 1.0000x reference)
#include <cuda_runtime.h>

#define N 2048
#define BATCH 16
#define THREADS 256
#define L2E 1.4426950408889634f

__device__ float g_bsuml[BATCH * N];   // Bsum[j] * log2(e)
__device__ float g_rowmax[BATCH * N];  // per-row max of w = a*l*s - Bsum*l

__device__ __forceinline__ float ex2(float x) {
    float y;
    asm("ex2.approx.f32 %0, %1;" : "=f"(y) : "f"(x));
    return y;
}

// ---- Kernel 1: Bsum (warp per j, short chains for accuracy), scaled by log2e
__global__ void __launch_bounds__(THREADS) bsum_kernel(const float* __restrict__ scores) {
    __shared__ float s[N];
    int b = blockIdx.y;
    const float* sp = scores + (size_t)b * N;
    for (int j = threadIdx.x; j < N; j += blockDim.x) s[j] = sp[j];
    __syncthreads();

    int warp = threadIdx.x >> 5;
    int lane = threadIdx.x & 31;
    int j = blockIdx.x * 8 + warp;          // 8 warps/block, N/8 blocks in x
    float sj = s[j];
    float acc = 0.0f;
    #pragma unroll 8
    for (int i = lane; i < N; i += 32)
        acc += fabsf(sj - s[i]);
    #pragma unroll
    for (int o = 16; o > 0; o >>= 1)
        acc += __shfl_xor_sync(0xFFFFFFFFu, acc, o);
    if (lane == 0) g_bsuml[(size_t)b * N + j] = acc * L2E;
}

// ---- Kernel 2: per-row max of w (warp per row, 8 rows/block, smem-resident)
__global__ void __launch_bounds__(THREADS) rowmax_kernel(const float* __restrict__ scores) {
    __shared__ float s[N];
    __shared__ float bl[N];
    int b = blockIdx.y;
    const float* sp = scores + (size_t)b * N;
    const float* bp = g_bsuml + (size_t)b * N;
    for (int j = threadIdx.x; j < N; j += blockDim.x) { s[j] = sp[j]; bl[j] = bp[j]; }
    __syncthreads();

    int warp = threadIdx.x >> 5;
    int lane = threadIdx.x & 31;
    int i = blockIdx.x * 8 + warp;          // row index
    float al = (float)(N - 1 - 2 * i) * L2E;
    float m = -INFINITY;
    #pragma unroll 8
    for (int k = lane; k < N; k += 32)
        m = fmaxf(m, fmaf(al, s[k], -bl[k]));
    #pragma unroll
    for (int o = 16; o > 0; o >>= 1)
        m = fmaxf(m, __shfl_xor_sync(0xFFFFFFFFu, m, o));
    if (lane == 0) g_rowmax[(size_t)b * N + i] = m;
}

// ---- Kernel 3: hot streaming kernel — FFMA + FSUB + EX2 + sum + scale + STG.128
__global__ void __launch_bounds__(THREADS) softmax_kernel(
    const float* __restrict__ scores, float* __restrict__ out)
{
    int i = blockIdx.x;
    int b = blockIdx.y;
    float al = (float)(N - 1 - 2 * i) * L2E;
    float m = __ldg(&g_rowmax[(size_t)b * N + i]);

    const float4* s4  = (const float4*)(scores  + (size_t)b * N);
    const float4* bs4 = (const float4*)(g_bsuml + (size_t)b * N);
    float4* o4 = (float4*)(out + ((size_t)b * N + i) * N);

    __shared__ float sh[THREADS / 32];

    int t = threadIdx.x;
    float e[8];
    float lsum = 0.0f;

    #pragma unroll
    for (int c = 0; c < 2; c++) {
        int idx = t + c * THREADS;
        float4 sv = s4[idx];
        float4 bv = bs4[idx];
        float e0 = ex2(fmaf(al, sv.x, -bv.x) - m);
        float e1 = ex2(fmaf(al, sv.y, -bv.y) - m);
        float e2 = ex2(fmaf(al, sv.z, -bv.z) - m);
        float e3 = ex2(fmaf(al, sv.w, -bv.w) - m);
        e[c * 4 + 0] = e0; e[c * 4 + 1] = e1;
        e[c * 4 + 2] = e2; e[c * 4 + 3] = e3;
        lsum += (e0 + e1) + (e2 + e3);
    }

    // single block-reduce-sum (one logical barrier phase)
    #pragma unroll
    for (int o = 16; o > 0; o >>= 1)
        lsum += __shfl_xor_sync(0xFFFFFFFFu, lsum, o);
    int wid = t >> 5, lane = t & 31;
    if (lane == 0) sh[wid] = lsum;
    __syncthreads();
    float total;
    {
        float v = (lane < (THREADS / 32)) ? sh[lane] : 0.0f;
        #pragma unroll
        for (int o = 4; o > 0; o >>= 1)
            v += __shfl_xor_sync(0xFFFFFFFFu, v, o);
        total = __shfl_sync(0xFFFFFFFFu, v, 0);   // valid within warp 0
        if (lane == 0) sh[wid] = v;               // broadcast via smem
    }
    __syncthreads();
    float inv = 1.0f / sh[0];

    #pragma unroll
    for (int c = 0; c < 2; c++) {
        int idx = t + c * THREADS;
        float4 r;
        r.x = e[c * 4 + 0] * inv;
        r.y = e[c * 4 + 1] * inv;
        r.z = e[c * 4 + 2] * inv;
        r.w = e[c * 4 + 3] * inv;
        __stcs(&o4[idx], r);
    }
}

extern "C" void kernel_launch(void* const* d_in, const int* in_sizes, int n_in,
                              void* d_out, int out_size) {
    const float* scores = (const float*)d_in[0];
    float* out = (float*)d_out;

    dim3 bgrid(N / 8, BATCH);
    bsum_kernel<<<bgrid, THREADS>>>(scores);
    rowmax_kernel<<<bgrid, THREADS>>>(scores);
    dim3 grid(N, BATCH);
    softmax_kernel<<<grid, THREADS>>>(scores, out);
}